// round 2
// baseline (speedup 1.0000x reference)
#include <cuda_runtime.h>

#define BATCH 8192
#define UNITS 256
#define NACT  16
#define HID   8

// scratch: action outputs of coagent layers 0 and 1 (integers stored as float)
__device__ float g_a0[BATCH * UNITS];
__device__ float g_a1[BATCH * UNITS];

// ---------------------------------------------------------------------------
// Fused coagent layer:
//   pre = x[B,F] @ W0^T  (W0 laid out as [U*H, F])
//   h0  = relu(pre + b0)            (done per 64x64 tile in-block)
//   h1  = relu(W1[u] h0 + b1[u])    (8x8 per unit)
//   q   = W2[u] h1 + b2[u]          (16x8 per unit)
//   out = argmax_a q  (first max on ties, matching jnp.argmax)
// Block tile: 64 batch rows x 8 units (=64 h-columns). 256 threads, 4x4 regs.
// Two-level accumulation (16-wide chunks) to minimize fp32 ordering error.
// ---------------------------------------------------------------------------
template <int F>
__global__ __launch_bounds__(256) void coagent_kernel(
    const float* __restrict__ x,    // [BATCH, F]
    const float* __restrict__ W0,   // [UNITS*HID, F]
    const float* __restrict__ b0,   // [UNITS*HID]
    const float* __restrict__ W1,   // [UNITS, HID, HID]
    const float* __restrict__ b1,   // [UNITS, HID]
    const float* __restrict__ W2,   // [UNITS, NACT, HID]
    const float* __restrict__ b2,   // [UNITS, NACT]
    float* __restrict__ aout)       // [BATCH, UNITS]
{
    __shared__ float xs[16][68];     // x tile, transposed: xs[k][row]
    __shared__ float ws[16][68];     // W0 tile, transposed: ws[k][col]
    __shared__ float hs[64][65];     // relu'd hidden tile [row][col]
    __shared__ float w1s[8][64];
    __shared__ float w2s[8][128];
    __shared__ float b1s[8][8];
    __shared__ float b2s[8][16];

    const int tid  = threadIdx.x;
    const int row0 = blockIdx.y * 64;          // batch rows
    const int col0 = blockIdx.x * 64;          // h-columns (= u*8 + h)
    const int u0   = blockIdx.x * 8;           // units

    // preload per-unit tiny-MLP weights
    for (int i = tid; i < 512; i += 256)  w1s[i >> 6][i & 63]  = W1[u0 * 64  + i];
    for (int i = tid; i < 1024; i += 256) w2s[i >> 7][i & 127] = W2[u0 * 128 + i];
    if (tid < 64)  b1s[tid >> 3][tid & 7]  = b1[u0 * 8  + tid];
    if (tid < 128) b2s[tid >> 4][tid & 15] = b2[u0 * 16 + tid];

    const int tx = tid & 15, ty = tid >> 4;
    const int tx4 = tx * 4,  ty4 = ty * 4;
    const int lrow = tid >> 2;            // 0..63 (row/col index for loads)
    const int lk   = (tid & 3) * 4;       // 0,4,8,12

    float acc[4][4];
#pragma unroll
    for (int i = 0; i < 4; i++)
#pragma unroll
        for (int j = 0; j < 4; j++) acc[i][j] = 0.0f;

    for (int k0 = 0; k0 < F; k0 += 16) {
        __syncthreads();
        float4 xa = *(const float4*)&x [(row0 + lrow) * F + k0 + lk];
        float4 wa = *(const float4*)&W0[(col0 + lrow) * F + k0 + lk];
        xs[lk + 0][lrow] = xa.x; xs[lk + 1][lrow] = xa.y;
        xs[lk + 2][lrow] = xa.z; xs[lk + 3][lrow] = xa.w;
        ws[lk + 0][lrow] = wa.x; ws[lk + 1][lrow] = wa.y;
        ws[lk + 2][lrow] = wa.z; ws[lk + 3][lrow] = wa.w;
        __syncthreads();

        // chunk accumulator (two-level sum: 16-term chunks into acc)
        float ch[4][4];
#pragma unroll
        for (int i = 0; i < 4; i++)
#pragma unroll
            for (int j = 0; j < 4; j++) ch[i][j] = 0.0f;

#pragma unroll
        for (int kk = 0; kk < 16; ++kk) {
            float4 a = *(const float4*)&xs[kk][ty4];
            float4 b = *(const float4*)&ws[kk][tx4];
            ch[0][0] += a.x * b.x; ch[0][1] += a.x * b.y;
            ch[0][2] += a.x * b.z; ch[0][3] += a.x * b.w;
            ch[1][0] += a.y * b.x; ch[1][1] += a.y * b.y;
            ch[1][2] += a.y * b.z; ch[1][3] += a.y * b.w;
            ch[2][0] += a.z * b.x; ch[2][1] += a.z * b.y;
            ch[2][2] += a.z * b.z; ch[2][3] += a.z * b.w;
            ch[3][0] += a.w * b.x; ch[3][1] += a.w * b.y;
            ch[3][2] += a.w * b.z; ch[3][3] += a.w * b.w;
        }
#pragma unroll
        for (int i = 0; i < 4; i++)
#pragma unroll
            for (int j = 0; j < 4; j++) acc[i][j] += ch[i][j];
    }

    // bias + relu into shared hidden tile
#pragma unroll
    for (int i = 0; i < 4; i++) {
#pragma unroll
        for (int j = 0; j < 4; j++) {
            float v = acc[i][j] + b0[col0 + tx4 + j];
            hs[ty4 + i][tx4 + j] = fmaxf(v, 0.0f);
        }
    }
    __syncthreads();

    // tiny-MLP + argmax epilogue: 64 rows x 8 units = 512 tasks
    for (int t = tid; t < 512; t += 256) {
        const int row = t & 63;
        const int uu  = t >> 6;
        float hv[8];
#pragma unroll
        for (int h = 0; h < 8; h++) hv[h] = hs[row][uu * 8 + h];

        float h1v[8];
#pragma unroll
        for (int g = 0; g < 8; g++) {
            float s = b1s[uu][g];
#pragma unroll
            for (int h = 0; h < 8; h++) s += w1s[uu][g * 8 + h] * hv[h];
            h1v[g] = fmaxf(s, 0.0f);
        }

        float best = -3.402823466e38f;
        int   arg  = 0;
#pragma unroll
        for (int a = 0; a < NACT; a++) {
            float q = b2s[uu][a];
#pragma unroll
            for (int g = 0; g < 8; g++) q += w2s[uu][a * 8 + g] * h1v[g];
            if (q > best) { best = q; arg = a; }   // strict > keeps first max
        }
        aout[(row0 + row) * UNITS + u0 + uu] = (float)arg;
    }
}

// ---------------------------------------------------------------------------
// Policy head: per row b: h = relu(PW0 @ a1_b + Pb0); h = relu(PW1 h + Pb1);
// out[b] = PW2 h + Pb2.  One warp per row.
// ---------------------------------------------------------------------------
__global__ __launch_bounds__(256) void policy_kernel(
    const float* __restrict__ a1,   // [BATCH, UNITS]
    const float* __restrict__ PW0,  // [HID, UNITS]
    const float* __restrict__ Pb0,  // [HID]
    const float* __restrict__ PW1,  // [HID, HID]
    const float* __restrict__ Pb1,  // [HID]
    const float* __restrict__ PW2,  // [1, HID]
    const float* __restrict__ Pb2,  // [1]
    float* __restrict__ out)        // [BATCH]
{
    const int lane = threadIdx.x & 31;
    const int row  = (blockIdx.x * blockDim.x + threadIdx.x) >> 5;
    if (row >= BATCH) return;

    const float* ar = a1 + row * UNITS;
    float av[8];
    {
        float4 v0 = *(const float4*)&ar[lane * 8];
        float4 v1 = *(const float4*)&ar[lane * 8 + 4];
        av[0] = v0.x; av[1] = v0.y; av[2] = v0.z; av[3] = v0.w;
        av[4] = v1.x; av[5] = v1.y; av[6] = v1.z; av[7] = v1.w;
    }

    float hp[8];
#pragma unroll
    for (int j = 0; j < 8; j++) {
        float s = 0.0f;
#pragma unroll
        for (int i = 0; i < 8; i++) s += PW0[j * UNITS + lane * 8 + i] * av[i];
#pragma unroll
        for (int off = 16; off; off >>= 1)
            s += __shfl_xor_sync(0xffffffffu, s, off);
        hp[j] = s;
    }

    if (lane == 0) {
        float h0v[8], h1v[8];
#pragma unroll
        for (int j = 0; j < 8; j++) h0v[j] = fmaxf(hp[j] + Pb0[j], 0.0f);
#pragma unroll
        for (int j = 0; j < 8; j++) {
            float s = Pb1[j];
#pragma unroll
            for (int i = 0; i < 8; i++) s += PW1[j * 8 + i] * h0v[i];
            h1v[j] = fmaxf(s, 0.0f);
        }
        float o = Pb2[0];
#pragma unroll
        for (int i = 0; i < 8; i++) o += PW2[i] * h1v[i];
        out[row] = o;
    }
}

extern "C" void kernel_launch(void* const* d_in, const int* in_sizes, int n_in,
                              void* d_out, int out_size) {
    (void)in_sizes; (void)n_in; (void)out_size;
    const float* state = (const float*)d_in[0];
    const float* W0_0  = (const float*)d_in[1];
    const float* b0_0  = (const float*)d_in[2];
    const float* W1_0  = (const float*)d_in[3];
    const float* b1_0  = (const float*)d_in[4];
    const float* W2_0  = (const float*)d_in[5];
    const float* b2_0  = (const float*)d_in[6];
    const float* W0_1  = (const float*)d_in[7];
    const float* b0_1  = (const float*)d_in[8];
    const float* W1_1  = (const float*)d_in[9];
    const float* b1_1  = (const float*)d_in[10];
    const float* W2_1  = (const float*)d_in[11];
    const float* b2_1  = (const float*)d_in[12];
    const float* PW0   = (const float*)d_in[13];
    const float* Pb0   = (const float*)d_in[14];
    const float* PW1   = (const float*)d_in[15];
    const float* Pb1   = (const float*)d_in[16];
    const float* PW2   = (const float*)d_in[17];
    const float* Pb2   = (const float*)d_in[18];
    float* out = (float*)d_out;

    float* a0 = nullptr;
    float* a1 = nullptr;
    cudaGetSymbolAddress((void**)&a0, g_a0);
    cudaGetSymbolAddress((void**)&a1, g_a1);

    dim3 grid(UNITS * HID / 64, BATCH / 64);   // (32, 128)

    coagent_kernel<1024><<<grid, 256>>>(state, W0_0, b0_0, W1_0, b1_0,
                                        W2_0, b2_0, a0);
    coagent_kernel<256><<<grid, 256>>>(a0, W0_1, b0_1, W1_1, b1_1,
                                       W2_1, b2_1, a1);
    policy_kernel<<<BATCH * 32 / 256, 256>>>(a1, PW0, Pb0, PW1, Pb1,
                                             PW2, Pb2, out);
}

// round 3
// speedup vs baseline: 1.1002x; 1.1002x over previous
#include <cuda_runtime.h>

#define BATCH 8192
#define UNITS 256
#define NACT  16
#define HID   8

// scratch: action outputs of coagent layers 0 and 1 (integers stored as float)
__device__ float g_a0[BATCH * UNITS];
__device__ float g_a1[BATCH * UNITS];

// Dynamic smem layout (floats):
//   xs: [2][16][132]  double-buffered x tile, transposed  (k, row)
//   ws: [2][16][132]  double-buffered W0 tile, transposed (k, col)
//   hs: [128][132]    relu'd hidden tile
#define XS_STRIDE 132
#define XS_ELEMS (2 * 16 * XS_STRIDE)
#define HS_STRIDE 132
#define DSM_BYTES ((2 * XS_ELEMS + 128 * HS_STRIDE) * 4)

// ---------------------------------------------------------------------------
// Fused coagent layer, 128x128 block tile, 8x8 per-thread register tile.
//   pre = x[B,F] @ W0^T ; h0 = relu(pre + b0)
//   h1 = relu(W1[u] h0 + b1[u]) ; q = W2[u] h1 + b2[u] ; out = argmax(q)
// Two-level accumulation (16-wide chunks) — numerics identical to R2 kernel.
// ---------------------------------------------------------------------------
template <int F>
__global__ __launch_bounds__(256, 1) void coagent_kernel(
    const float* __restrict__ x,    // [BATCH, F]
    const float* __restrict__ W0,   // [UNITS*HID, F]
    const float* __restrict__ b0,   // [UNITS*HID]
    const float* __restrict__ W1,   // [UNITS, HID, HID]
    const float* __restrict__ b1,   // [UNITS, HID]
    const float* __restrict__ W2,   // [UNITS, NACT, HID]
    const float* __restrict__ b2,   // [UNITS, NACT]
    float* __restrict__ aout)       // [BATCH, UNITS]
{
    extern __shared__ __align__(16) float dsm[];
    float* xsb = dsm;                    // [2][16][132]
    float* wsb = dsm + XS_ELEMS;         // [2][16][132]
    float* hsb = dsm + 2 * XS_ELEMS;     // [128][132]

    __shared__ float w1s[16][64];
    __shared__ float w2s[16][128];
    __shared__ float b1s[16][8];
    __shared__ float b2s[16][16];

    const int tid  = threadIdx.x;
    const int row0 = blockIdx.y * 128;   // batch rows
    const int col0 = blockIdx.x * 128;   // h-columns (= u*8 + h)
    const int u0   = blockIdx.x * 16;    // units

    // preload per-unit tiny-MLP weights
    for (int i = tid; i < 1024; i += 256) w1s[i >> 6][i & 63]  = W1[u0 * 64  + i];
    for (int i = tid; i < 2048; i += 256) w2s[i >> 7][i & 127] = W2[u0 * 128 + i];
    if (tid < 128) b1s[tid >> 3][tid & 7] = b1[u0 * 8 + tid];
    b2s[tid >> 4][tid & 15] = b2[u0 * 16 + tid];

    const int tx = tid & 15, ty = tid >> 4;
    const int tx8 = tx * 8,  ty8 = ty * 8;
    const int lrow = tid >> 1;            // 0..127
    const int lk8  = (tid & 1) * 8;       // 0 or 8

    const float* xrow = x  + (long)(row0 + lrow) * F + lk8;
    const float* wrow = W0 + (long)(col0 + lrow) * F + lk8;

    float acc[8][8];
#pragma unroll
    for (int i = 0; i < 8; i++)
#pragma unroll
        for (int j = 0; j < 8; j++) acc[i][j] = 0.0f;

#define XS(b, k, r) xsb[((b) * 16 + (k)) * XS_STRIDE + (r)]
#define WS(b, k, r) wsb[((b) * 16 + (k)) * XS_STRIDE + (r)]

    // preload chunk 0 into buffer 0
    {
        float4 xa = *(const float4*)xrow;
        float4 xb = *(const float4*)(xrow + 4);
        float4 wa = *(const float4*)wrow;
        float4 wb = *(const float4*)(wrow + 4);
        XS(0, lk8 + 0, lrow) = xa.x; XS(0, lk8 + 1, lrow) = xa.y;
        XS(0, lk8 + 2, lrow) = xa.z; XS(0, lk8 + 3, lrow) = xa.w;
        XS(0, lk8 + 4, lrow) = xb.x; XS(0, lk8 + 5, lrow) = xb.y;
        XS(0, lk8 + 6, lrow) = xb.z; XS(0, lk8 + 7, lrow) = xb.w;
        WS(0, lk8 + 0, lrow) = wa.x; WS(0, lk8 + 1, lrow) = wa.y;
        WS(0, lk8 + 2, lrow) = wa.z; WS(0, lk8 + 3, lrow) = wa.w;
        WS(0, lk8 + 4, lrow) = wb.x; WS(0, lk8 + 5, lrow) = wb.y;
        WS(0, lk8 + 6, lrow) = wb.z; WS(0, lk8 + 7, lrow) = wb.w;
    }
    __syncthreads();

    const int NC = F / 16;
    int buf = 0;
    for (int c = 0; c < NC; ++c, buf ^= 1) {
        // prefetch next chunk (gmem -> regs), overlapped with compute
        float4 xa, xb, wa, wb;
        if (c + 1 < NC) {
            const float* xp = xrow + (c + 1) * 16;
            const float* wp = wrow + (c + 1) * 16;
            xa = *(const float4*)xp; xb = *(const float4*)(xp + 4);
            wa = *(const float4*)wp; wb = *(const float4*)(wp + 4);
        }

        // two-level sum: 16-term chunk accumulator, then add into acc
        float ch[8][8];
#pragma unroll
        for (int i = 0; i < 8; i++)
#pragma unroll
            for (int j = 0; j < 8; j++) ch[i][j] = 0.0f;

#pragma unroll
        for (int kk = 0; kk < 16; ++kk) {
            float av[8], bv[8];
            float4 a0 = *(const float4*)&XS(buf, kk, ty8);
            float4 a1 = *(const float4*)&XS(buf, kk, ty8 + 4);
            float4 bq0 = *(const float4*)&WS(buf, kk, tx8);
            float4 bq1 = *(const float4*)&WS(buf, kk, tx8 + 4);
            av[0] = a0.x; av[1] = a0.y; av[2] = a0.z; av[3] = a0.w;
            av[4] = a1.x; av[5] = a1.y; av[6] = a1.z; av[7] = a1.w;
            bv[0] = bq0.x; bv[1] = bq0.y; bv[2] = bq0.z; bv[3] = bq0.w;
            bv[4] = bq1.x; bv[5] = bq1.y; bv[6] = bq1.z; bv[7] = bq1.w;
#pragma unroll
            for (int i = 0; i < 8; i++)
#pragma unroll
                for (int j = 0; j < 8; j++) ch[i][j] += av[i] * bv[j];
        }
#pragma unroll
        for (int i = 0; i < 8; i++)
#pragma unroll
            for (int j = 0; j < 8; j++) acc[i][j] += ch[i][j];

        if (c + 1 < NC) {
            const int nb = buf ^ 1;
            XS(nb, lk8 + 0, lrow) = xa.x; XS(nb, lk8 + 1, lrow) = xa.y;
            XS(nb, lk8 + 2, lrow) = xa.z; XS(nb, lk8 + 3, lrow) = xa.w;
            XS(nb, lk8 + 4, lrow) = xb.x; XS(nb, lk8 + 5, lrow) = xb.y;
            XS(nb, lk8 + 6, lrow) = xb.z; XS(nb, lk8 + 7, lrow) = xb.w;
            WS(nb, lk8 + 0, lrow) = wa.x; WS(nb, lk8 + 1, lrow) = wa.y;
            WS(nb, lk8 + 2, lrow) = wa.z; WS(nb, lk8 + 3, lrow) = wa.w;
            WS(nb, lk8 + 4, lrow) = wb.x; WS(nb, lk8 + 5, lrow) = wb.y;
            WS(nb, lk8 + 6, lrow) = wb.z; WS(nb, lk8 + 7, lrow) = wb.w;
        }
        __syncthreads();
    }

    // bias + relu into shared hidden tile
#pragma unroll
    for (int i = 0; i < 8; i++) {
#pragma unroll
        for (int j = 0; j < 8; j++) {
            float v = acc[i][j] + b0[col0 + tx8 + j];
            hsb[(ty8 + i) * HS_STRIDE + tx8 + j] = fmaxf(v, 0.0f);
        }
    }
    __syncthreads();

    // tiny-MLP + argmax epilogue: 128 rows x 16 units = 2048 tasks
    for (int t = tid; t < 2048; t += 256) {
        const int row = t >> 4;       // consecutive lanes share row: coalesced out
        const int uu  = t & 15;
        float hv[8];
        {
            float4 h0 = *(const float4*)&hsb[row * HS_STRIDE + uu * 8];
            float4 h1 = *(const float4*)&hsb[row * HS_STRIDE + uu * 8 + 4];
            hv[0] = h0.x; hv[1] = h0.y; hv[2] = h0.z; hv[3] = h0.w;
            hv[4] = h1.x; hv[5] = h1.y; hv[6] = h1.z; hv[7] = h1.w;
        }

        float h1v[8];
#pragma unroll
        for (int g = 0; g < 8; g++) {
            float s = b1s[uu][g];
#pragma unroll
            for (int h = 0; h < 8; h++) s += w1s[uu][g * 8 + h] * hv[h];
            h1v[g] = fmaxf(s, 0.0f);
        }

        float best = -3.402823466e38f;
        int   arg  = 0;
#pragma unroll
        for (int a = 0; a < NACT; a++) {
            float q = b2s[uu][a];
#pragma unroll
            for (int g = 0; g < 8; g++) q += w2s[uu][a * 8 + g] * h1v[g];
            if (q > best) { best = q; arg = a; }   // strict > keeps first max
        }
        aout[(long)(row0 + row) * UNITS + u0 + uu] = (float)arg;
    }
}

// ---------------------------------------------------------------------------
// Policy head: one warp per row.
// ---------------------------------------------------------------------------
__global__ __launch_bounds__(256) void policy_kernel(
    const float* __restrict__ a1,   // [BATCH, UNITS]
    const float* __restrict__ PW0,  // [HID, UNITS]
    const float* __restrict__ Pb0,  // [HID]
    const float* __restrict__ PW1,  // [HID, HID]
    const float* __restrict__ Pb1,  // [HID]
    const float* __restrict__ PW2,  // [1, HID]
    const float* __restrict__ Pb2,  // [1]
    float* __restrict__ out)        // [BATCH]
{
    const int lane = threadIdx.x & 31;
    const int row  = (blockIdx.x * blockDim.x + threadIdx.x) >> 5;
    if (row >= BATCH) return;

    const float* ar = a1 + (long)row * UNITS;
    float av[8];
    {
        float4 v0 = *(const float4*)&ar[lane * 8];
        float4 v1 = *(const float4*)&ar[lane * 8 + 4];
        av[0] = v0.x; av[1] = v0.y; av[2] = v0.z; av[3] = v0.w;
        av[4] = v1.x; av[5] = v1.y; av[6] = v1.z; av[7] = v1.w;
    }

    float hp[8];
#pragma unroll
    for (int j = 0; j < 8; j++) {
        float s = 0.0f;
#pragma unroll
        for (int i = 0; i < 8; i++) s += PW0[j * UNITS + lane * 8 + i] * av[i];
#pragma unroll
        for (int off = 16; off; off >>= 1)
            s += __shfl_xor_sync(0xffffffffu, s, off);
        hp[j] = s;
    }

    if (lane == 0) {
        float h0v[8], h1v[8];
#pragma unroll
        for (int j = 0; j < 8; j++) h0v[j] = fmaxf(hp[j] + Pb0[j], 0.0f);
#pragma unroll
        for (int j = 0; j < 8; j++) {
            float s = Pb1[j];
#pragma unroll
            for (int i = 0; i < 8; i++) s += PW1[j * 8 + i] * h0v[i];
            h1v[j] = fmaxf(s, 0.0f);
        }
        float o = Pb2[0];
#pragma unroll
        for (int i = 0; i < 8; i++) o += PW2[i] * h1v[i];
        out[row] = o;
    }
}

extern "C" void kernel_launch(void* const* d_in, const int* in_sizes, int n_in,
                              void* d_out, int out_size) {
    (void)in_sizes; (void)n_in; (void)out_size;
    const float* state = (const float*)d_in[0];
    const float* W0_0  = (const float*)d_in[1];
    const float* b0_0  = (const float*)d_in[2];
    const float* W1_0  = (const float*)d_in[3];
    const float* b1_0  = (const float*)d_in[4];
    const float* W2_0  = (const float*)d_in[5];
    const float* b2_0  = (const float*)d_in[6];
    const float* W0_1  = (const float*)d_in[7];
    const float* b0_1  = (const float*)d_in[8];
    const float* W1_1  = (const float*)d_in[9];
    const float* b1_1  = (const float*)d_in[10];
    const float* W2_1  = (const float*)d_in[11];
    const float* b2_1  = (const float*)d_in[12];
    const float* PW0   = (const float*)d_in[13];
    const float* Pb0   = (const float*)d_in[14];
    const float* PW1   = (const float*)d_in[15];
    const float* Pb1   = (const float*)d_in[16];
    const float* PW2   = (const float*)d_in[17];
    const float* Pb2   = (const float*)d_in[18];
    float* out = (float*)d_out;

    float* a0 = nullptr;
    float* a1 = nullptr;
    cudaGetSymbolAddress((void**)&a0, g_a0);
    cudaGetSymbolAddress((void**)&a1, g_a1);

    static int attr_done = 0;
    if (!attr_done) {
        cudaFuncSetAttribute(coagent_kernel<1024>,
                             cudaFuncAttributeMaxDynamicSharedMemorySize, DSM_BYTES);
        cudaFuncSetAttribute(coagent_kernel<256>,
                             cudaFuncAttributeMaxDynamicSharedMemorySize, DSM_BYTES);
        attr_done = 1;
    }

    dim3 grid(UNITS * HID / 128, BATCH / 128);   // (16, 64)

    coagent_kernel<1024><<<grid, 256, DSM_BYTES>>>(state, W0_0, b0_0, W1_0, b1_0,
                                                   W2_0, b2_0, a0);
    coagent_kernel<256><<<grid, 256, DSM_BYTES>>>(a0, W0_1, b0_1, W1_1, b1_1,
                                                  W2_1, b2_1, a1);
    policy_kernel<<<BATCH * 32 / 256, 256>>>(a1, PW0, Pb0, PW1, Pb1,
                                             PW2, Pb2, out);
}

// round 4
// speedup vs baseline: 1.1235x; 1.0211x over previous
#include <cuda_runtime.h>

#define BATCH 8192
#define UNITS 256
#define NACT  16
#define HID   8

typedef unsigned long long ull;

// packed fp32x2 ops (sm_100+). Each lane is an exact IEEE-rn fp32 op, so the
// packed version is bit-identical to the scalar code it replaces.
#define FMA2(acc, a, b) asm("fma.rn.f32x2 %0, %1, %2, %0;" : "+l"(acc) : "l"(a), "l"(b))
#define ADD2(acc, v)    asm("add.rn.f32x2 %0, %1, %0;"     : "+l"(acc) : "l"(v))
#define DUP2(d, s)      asm("mov.b64 %0, {%1, %1};"        : "=l"(d)   : "r"(s))

union F2U { ull u; float2 f; };

// scratch: action outputs of coagent layers 0 and 1 (integers stored as float)
__device__ float g_a0[BATCH * UNITS];
__device__ float g_a1[BATCH * UNITS];

// Dynamic smem layout (floats):
//   xs: [2][16][132]  double-buffered x tile, transposed  (k, row)
//   ws: [2][16][132]  double-buffered W0 tile, transposed (k, col)
//   hs: [128][132]    relu'd hidden tile
#define XS_STRIDE 132
#define XS_ELEMS (2 * 16 * XS_STRIDE)
#define HS_STRIDE 132
#define DSM_BYTES ((2 * XS_ELEMS + 128 * HS_STRIDE) * 4)

// ---------------------------------------------------------------------------
// Fused coagent layer, 128x128 block tile, 8x8 per-thread register tile,
// inner product via packed fma.rn.f32x2 (FFMA2). Two-level accumulation
// (16-wide chunks) — numerics bit-identical to R2/R3 kernels.
// ---------------------------------------------------------------------------
template <int F>
__global__ __launch_bounds__(256, 1) void coagent_kernel(
    const float* __restrict__ x,    // [BATCH, F]
    const float* __restrict__ W0,   // [UNITS*HID, F]
    const float* __restrict__ b0,   // [UNITS*HID]
    const float* __restrict__ W1,   // [UNITS, HID, HID]
    const float* __restrict__ b1,   // [UNITS, HID]
    const float* __restrict__ W2,   // [UNITS, NACT, HID]
    const float* __restrict__ b2,   // [UNITS, NACT]
    float* __restrict__ aout)       // [BATCH, UNITS]
{
    extern __shared__ __align__(16) float dsm[];
    float* xsb = dsm;                    // [2][16][132]
    float* wsb = dsm + XS_ELEMS;         // [2][16][132]
    float* hsb = dsm + 2 * XS_ELEMS;     // [128][132]

    __shared__ float w1s[16][64];
    __shared__ float w2s[16][128];
    __shared__ float b1s[16][8];
    __shared__ float b2s[16][16];

    const int tid  = threadIdx.x;
    const int row0 = blockIdx.y * 128;   // batch rows
    const int col0 = blockIdx.x * 128;   // h-columns (= u*8 + h)
    const int u0   = blockIdx.x * 16;    // units

    // preload per-unit tiny-MLP weights
    for (int i = tid; i < 1024; i += 256) w1s[i >> 6][i & 63]  = W1[u0 * 64  + i];
    for (int i = tid; i < 2048; i += 256) w2s[i >> 7][i & 127] = W2[u0 * 128 + i];
    if (tid < 128) b1s[tid >> 3][tid & 7] = b1[u0 * 8 + tid];
    b2s[tid >> 4][tid & 15] = b2[u0 * 16 + tid];

    const int tx = tid & 15, ty = tid >> 4;
    const int tx8 = tx * 8,  ty8 = ty * 8;
    const int lrow = tid >> 1;            // 0..127
    const int lk8  = (tid & 1) * 8;       // 0 or 8

    const float* xrow = x  + (long)(row0 + lrow) * F + lk8;
    const float* wrow = W0 + (long)(col0 + lrow) * F + lk8;

    // packed accumulators: acc2[i][jp] holds cols (tx8+2jp, tx8+2jp+1)
    ull acc2[8][4];
#pragma unroll
    for (int i = 0; i < 8; i++)
#pragma unroll
        for (int j = 0; j < 4; j++) acc2[i][j] = 0ull;   // {+0.0f, +0.0f}

#define XS(b, k, r) xsb[((b) * 16 + (k)) * XS_STRIDE + (r)]
#define WS(b, k, r) wsb[((b) * 16 + (k)) * XS_STRIDE + (r)]

    // preload chunk 0 into buffer 0
    {
        float4 xa = *(const float4*)xrow;
        float4 xb = *(const float4*)(xrow + 4);
        float4 wa = *(const float4*)wrow;
        float4 wb = *(const float4*)(wrow + 4);
        XS(0, lk8 + 0, lrow) = xa.x; XS(0, lk8 + 1, lrow) = xa.y;
        XS(0, lk8 + 2, lrow) = xa.z; XS(0, lk8 + 3, lrow) = xa.w;
        XS(0, lk8 + 4, lrow) = xb.x; XS(0, lk8 + 5, lrow) = xb.y;
        XS(0, lk8 + 6, lrow) = xb.z; XS(0, lk8 + 7, lrow) = xb.w;
        WS(0, lk8 + 0, lrow) = wa.x; WS(0, lk8 + 1, lrow) = wa.y;
        WS(0, lk8 + 2, lrow) = wa.z; WS(0, lk8 + 3, lrow) = wa.w;
        WS(0, lk8 + 4, lrow) = wb.x; WS(0, lk8 + 5, lrow) = wb.y;
        WS(0, lk8 + 6, lrow) = wb.z; WS(0, lk8 + 7, lrow) = wb.w;
    }
    __syncthreads();

    const int NC = F / 16;
    int buf = 0;
    for (int c = 0; c < NC; ++c, buf ^= 1) {
        // prefetch next chunk (gmem -> regs), overlapped with compute
        float4 xa, xb, wa, wb;
        if (c + 1 < NC) {
            const float* xp = xrow + (c + 1) * 16;
            const float* wp = wrow + (c + 1) * 16;
            xa = *(const float4*)xp; xb = *(const float4*)(xp + 4);
            wa = *(const float4*)wp; wb = *(const float4*)(wp + 4);
        }

        // two-level sum: 16-term chunk accumulator (packed), add into acc
        ull ch2[8][4];
#pragma unroll
        for (int i = 0; i < 8; i++)
#pragma unroll
            for (int j = 0; j < 4; j++) ch2[i][j] = 0ull;

#pragma unroll
        for (int kk = 0; kk < 16; ++kk) {
            float4 a0 = *(const float4*)&XS(buf, kk, ty8);
            float4 a1 = *(const float4*)&XS(buf, kk, ty8 + 4);
            ulonglong2 bq0 = *(const ulonglong2*)&WS(buf, kk, tx8);
            ulonglong2 bq1 = *(const ulonglong2*)&WS(buf, kk, tx8 + 4);
            ull bv2[4];
            bv2[0] = bq0.x; bv2[1] = bq0.y; bv2[2] = bq1.x; bv2[3] = bq1.y;
            float av[8];
            av[0] = a0.x; av[1] = a0.y; av[2] = a0.z; av[3] = a0.w;
            av[4] = a1.x; av[5] = a1.y; av[6] = a1.z; av[7] = a1.w;
#pragma unroll
            for (int i = 0; i < 8; i++) {
                ull ad;
                DUP2(ad, __float_as_uint(av[i]));
                FMA2(ch2[i][0], ad, bv2[0]);
                FMA2(ch2[i][1], ad, bv2[1]);
                FMA2(ch2[i][2], ad, bv2[2]);
                FMA2(ch2[i][3], ad, bv2[3]);
            }
        }
#pragma unroll
        for (int i = 0; i < 8; i++)
#pragma unroll
            for (int j = 0; j < 4; j++) ADD2(acc2[i][j], ch2[i][j]);

        if (c + 1 < NC) {
            const int nb = buf ^ 1;
            XS(nb, lk8 + 0, lrow) = xa.x; XS(nb, lk8 + 1, lrow) = xa.y;
            XS(nb, lk8 + 2, lrow) = xa.z; XS(nb, lk8 + 3, lrow) = xa.w;
            XS(nb, lk8 + 4, lrow) = xb.x; XS(nb, lk8 + 5, lrow) = xb.y;
            XS(nb, lk8 + 6, lrow) = xb.z; XS(nb, lk8 + 7, lrow) = xb.w;
            WS(nb, lk8 + 0, lrow) = wa.x; WS(nb, lk8 + 1, lrow) = wa.y;
            WS(nb, lk8 + 2, lrow) = wa.z; WS(nb, lk8 + 3, lrow) = wa.w;
            WS(nb, lk8 + 4, lrow) = wb.x; WS(nb, lk8 + 5, lrow) = wb.y;
            WS(nb, lk8 + 6, lrow) = wb.z; WS(nb, lk8 + 7, lrow) = wb.w;
        }
        __syncthreads();
    }

    // bias + relu into shared hidden tile (unpack packed accumulators)
#pragma unroll
    for (int i = 0; i < 8; i++) {
#pragma unroll
        for (int j = 0; j < 4; j++) {
            F2U t; t.u = acc2[i][j];
            float v0 = t.f.x + b0[col0 + tx8 + 2 * j];
            float v1 = t.f.y + b0[col0 + tx8 + 2 * j + 1];
            hsb[(ty8 + i) * HS_STRIDE + tx8 + 2 * j]     = fmaxf(v0, 0.0f);
            hsb[(ty8 + i) * HS_STRIDE + tx8 + 2 * j + 1] = fmaxf(v1, 0.0f);
        }
    }
    __syncthreads();

    // tiny-MLP + argmax epilogue: 128 rows x 16 units = 2048 tasks
    for (int t = tid; t < 2048; t += 256) {
        const int row = t >> 4;       // consecutive lanes share row: coalesced out
        const int uu  = t & 15;
        float hv[8];
        {
            float4 h0 = *(const float4*)&hsb[row * HS_STRIDE + uu * 8];
            float4 h1 = *(const float4*)&hsb[row * HS_STRIDE + uu * 8 + 4];
            hv[0] = h0.x; hv[1] = h0.y; hv[2] = h0.z; hv[3] = h0.w;
            hv[4] = h1.x; hv[5] = h1.y; hv[6] = h1.z; hv[7] = h1.w;
        }

        float h1v[8];
#pragma unroll
        for (int g = 0; g < 8; g++) {
            float s = b1s[uu][g];
#pragma unroll
            for (int h = 0; h < 8; h++) s += w1s[uu][g * 8 + h] * hv[h];
            h1v[g] = fmaxf(s, 0.0f);
        }

        float best = -3.402823466e38f;
        int   arg  = 0;
#pragma unroll
        for (int a = 0; a < NACT; a++) {
            float q = b2s[uu][a];
#pragma unroll
            for (int g = 0; g < 8; g++) q += w2s[uu][a * 8 + g] * h1v[g];
            if (q > best) { best = q; arg = a; }   // strict > keeps first max
        }
        aout[(long)(row0 + row) * UNITS + u0 + uu] = (float)arg;
    }
}

// ---------------------------------------------------------------------------
// Policy head: one warp per row.
// ---------------------------------------------------------------------------
__global__ __launch_bounds__(256) void policy_kernel(
    const float* __restrict__ a1,   // [BATCH, UNITS]
    const float* __restrict__ PW0,  // [HID, UNITS]
    const float* __restrict__ Pb0,  // [HID]
    const float* __restrict__ PW1,  // [HID, HID]
    const float* __restrict__ Pb1,  // [HID]
    const float* __restrict__ PW2,  // [1, HID]
    const float* __restrict__ Pb2,  // [1]
    float* __restrict__ out)        // [BATCH]
{
    const int lane = threadIdx.x & 31;
    const int row  = (blockIdx.x * blockDim.x + threadIdx.x) >> 5;
    if (row >= BATCH) return;

    const float* ar = a1 + (long)row * UNITS;
    float av[8];
    {
        float4 v0 = *(const float4*)&ar[lane * 8];
        float4 v1 = *(const float4*)&ar[lane * 8 + 4];
        av[0] = v0.x; av[1] = v0.y; av[2] = v0.z; av[3] = v0.w;
        av[4] = v1.x; av[5] = v1.y; av[6] = v1.z; av[7] = v1.w;
    }

    float hp[8];
#pragma unroll
    for (int j = 0; j < 8; j++) {
        float s = 0.0f;
#pragma unroll
        for (int i = 0; i < 8; i++) s += PW0[j * UNITS + lane * 8 + i] * av[i];
#pragma unroll
        for (int off = 16; off; off >>= 1)
            s += __shfl_xor_sync(0xffffffffu, s, off);
        hp[j] = s;
    }

    if (lane == 0) {
        float h0v[8], h1v[8];
#pragma unroll
        for (int j = 0; j < 8; j++) h0v[j] = fmaxf(hp[j] + Pb0[j], 0.0f);
#pragma unroll
        for (int j = 0; j < 8; j++) {
            float s = Pb1[j];
#pragma unroll
            for (int i = 0; i < 8; i++) s += PW1[j * 8 + i] * h0v[i];
            h1v[j] = fmaxf(s, 0.0f);
        }
        float o = Pb2[0];
#pragma unroll
        for (int i = 0; i < 8; i++) o += PW2[i] * h1v[i];
        out[row] = o;
    }
}

extern "C" void kernel_launch(void* const* d_in, const int* in_sizes, int n_in,
                              void* d_out, int out_size) {
    (void)in_sizes; (void)n_in; (void)out_size;
    const float* state = (const float*)d_in[0];
    const float* W0_0  = (const float*)d_in[1];
    const float* b0_0  = (const float*)d_in[2];
    const float* W1_0  = (const float*)d_in[3];
    const float* b1_0  = (const float*)d_in[4];
    const float* W2_0  = (const float*)d_in[5];
    const float* b2_0  = (const float*)d_in[6];
    const float* W0_1  = (const float*)d_in[7];
    const float* b0_1  = (const float*)d_in[8];
    const float* W1_1  = (const float*)d_in[9];
    const float* b1_1  = (const float*)d_in[10];
    const float* W2_1  = (const float*)d_in[11];
    const float* b2_1  = (const float*)d_in[12];
    const float* PW0   = (const float*)d_in[13];
    const float* Pb0   = (const float*)d_in[14];
    const float* PW1   = (const float*)d_in[15];
    const float* Pb1   = (const float*)d_in[16];
    const float* PW2   = (const float*)d_in[17];
    const float* Pb2   = (const float*)d_in[18];
    float* out = (float*)d_out;

    float* a0 = nullptr;
    float* a1 = nullptr;
    cudaGetSymbolAddress((void**)&a0, g_a0);
    cudaGetSymbolAddress((void**)&a1, g_a1);

    static int attr_done = 0;
    if (!attr_done) {
        cudaFuncSetAttribute(coagent_kernel<1024>,
                             cudaFuncAttributeMaxDynamicSharedMemorySize, DSM_BYTES);
        cudaFuncSetAttribute(coagent_kernel<256>,
                             cudaFuncAttributeMaxDynamicSharedMemorySize, DSM_BYTES);
        attr_done = 1;
    }

    dim3 grid(UNITS * HID / 128, BATCH / 128);   // (16, 64)

    coagent_kernel<1024><<<grid, 256, DSM_BYTES>>>(state, W0_0, b0_0, W1_0, b1_0,
                                                   W2_0, b2_0, a0);
    coagent_kernel<256><<<grid, 256, DSM_BYTES>>>(a0, W0_1, b0_1, W1_1, b1_1,
                                                  W2_1, b2_1, a1);
    policy_kernel<<<BATCH * 32 / 256, 256>>>(a1, PW0, Pb0, PW1, Pb1,
                                             PW2, Pb2, out);
}